// round 1
// baseline (speedup 1.0000x reference)
#include <cuda_runtime.h>
#include <cuda_bf16.h>
#include <math.h>

// ---------------- problem constants ----------------
#define BATCH 32
#define SEQ   197          // 14*14 + 1
#define MTOK  (BATCH*SEQ)  // 6304
#define HID   768
#define NH    12
#define DH    64
#define INTER 3072
#define NLAYER 12
#define NCLS  1000
#define GP    14
#define PSZ   16
#define IMG   224
#define MPATCH (BATCH*GP*GP)   // 6272

// ---------------- scratch (device globals; no cudaMalloc allowed) ----------------
__device__ float g_h  [MTOK*HID];
__device__ float g_hn [MTOK*HID];
__device__ float g_q  [MTOK*HID];
__device__ float g_k  [MTOK*HID];
__device__ float g_v  [MTOK*HID];
__device__ float g_att[MTOK*HID];     // also reused as patch-embed GEMM output
__device__ float g_m1 [MTOK*INTER];
__device__ float g_xp [MPATCH*HID];
__device__ float g_wp [HID*HID];      // transposed conv_w

// ---------------- small kernels ----------------
__global__ void transpose_w(const float* __restrict__ conv_w, float* __restrict__ wp) {
    int idx = blockIdx.x * blockDim.x + threadIdx.x;   // over 768*768
    if (idx >= HID*HID) return;
    int kk = idx / HID, d = idx % HID;
    wp[kk*HID + d] = conv_w[d*HID + kk];
}

__global__ void patchify(const float* __restrict__ x, float* __restrict__ xp) {
    int idx = blockIdx.x * blockDim.x + threadIdx.x;   // over 6272*768
    if (idx >= MPATCH*HID) return;
    int m  = idx / HID;
    int kk = idx % HID;
    int b = m / (GP*GP), r = m % (GP*GP);
    int i = r / GP, j = r % GP;
    int c = kk / (PSZ*PSZ), rem = kk % (PSZ*PSZ);
    int p = rem / PSZ, q = rem % PSZ;
    xp[idx] = x[ ((size_t)(b*3 + c)*IMG + (i*PSZ + p))*IMG + (j*PSZ + q) ];
}

__global__ void build_h(const float* __restrict__ xe, const float* __restrict__ cls,
                        const float* __restrict__ pos, float* __restrict__ h) {
    int idx = blockIdx.x * blockDim.x + threadIdx.x;   // over 6304*768
    if (idx >= MTOK*HID) return;
    int m = idx / HID, d = idx % HID;
    int b = m / SEQ, s = m % SEQ;
    float pv = pos[s*HID + d];
    float v;
    if (s == 0) v = cls[d] + pv;
    else        v = xe[(size_t)(b*(GP*GP) + (s-1))*HID + d] + pv;
    h[idx] = v;
}

__global__ void layernorm_k(const float* __restrict__ x, const float* __restrict__ scale,
                            const float* __restrict__ bias, float* __restrict__ out) {
    int m = blockIdx.x;
    int tid = threadIdx.x;                 // 256 threads, 768 elems
    const float* row = x + (size_t)m*HID;
    float v0 = row[tid], v1 = row[tid+256], v2 = row[tid+512];
    __shared__ float red[256];
    red[tid] = v0 + v1 + v2;
    __syncthreads();
    #pragma unroll
    for (int o = 128; o > 0; o >>= 1) { if (tid < o) red[tid] += red[tid+o]; __syncthreads(); }
    float mu = red[0] * (1.0f/768.0f);
    __syncthreads();
    float d0 = v0-mu, d1 = v1-mu, d2 = v2-mu;
    red[tid] = d0*d0 + d1*d1 + d2*d2;
    __syncthreads();
    #pragma unroll
    for (int o = 128; o > 0; o >>= 1) { if (tid < o) red[tid] += red[tid+o]; __syncthreads(); }
    float rstd = rsqrtf(red[0] * (1.0f/768.0f) + 1e-5f);
    float* orow = out + (size_t)m*HID;
    orow[tid]     = d0*rstd*scale[tid]     + bias[tid];
    orow[tid+256] = d1*rstd*scale[tid+256] + bias[tid+256];
    orow[tid+512] = d2*rstd*scale[tid+512] + bias[tid+512];
}

// ---------------- SGEMM: C[M,N] = A[M,K] @ B + bias (+resid)(+gelu) ----------------
// B addressing: hstride==0 : row-major [K,N] with leading dim ldb
//               hstride>0  : head-blocked [h][k][64]: elem(k,n) at (n>>6)*hstride + k*64 + (n&63)
__global__ __launch_bounds__(256) void sgemm_k(
    const float* __restrict__ A, const float* __restrict__ B, float* __restrict__ C,
    int M, int N, int K, int ldb, int hstride,
    const float* __restrict__ bias, const float* __restrict__ resid, int act)
{
    __shared__ float As[8][128];
    __shared__ float Bs[8][128];
    const int tid = threadIdx.x;
    const int m0 = blockIdx.y * 128;
    const int n0 = blockIdx.x * 128;
    const int tx = tid & 15;
    const int ty = tid >> 4;
    const int arow = tid >> 1;
    const int acol = (tid & 1) << 2;
    const int brow = tid >> 5;
    const int bcol = (tid & 31) << 2;

    float acc[8][8];
    #pragma unroll
    for (int i = 0; i < 8; i++)
        #pragma unroll
        for (int j = 0; j < 8; j++) acc[i][j] = 0.0f;

    const int gm_a = m0 + arow;
    const bool a_ok = (gm_a < M);

    for (int k0 = 0; k0 < K; k0 += 8) {
        float4 av = make_float4(0.f, 0.f, 0.f, 0.f);
        if (a_ok) av = *reinterpret_cast<const float4*>(A + (size_t)gm_a*K + k0 + acol);
        As[acol+0][arow] = av.x; As[acol+1][arow] = av.y;
        As[acol+2][arow] = av.z; As[acol+3][arow] = av.w;

        if (hstride) {
            const int kk = k0 + brow;
            #pragma unroll
            for (int j = 0; j < 4; j++) {
                int n = n0 + bcol + j;
                Bs[brow][bcol+j] = B[(size_t)(n >> 6)*hstride + kk*64 + (n & 63)];
            }
        } else {
            *reinterpret_cast<float4*>(&Bs[brow][bcol]) =
                *reinterpret_cast<const float4*>(B + (size_t)(k0+brow)*ldb + n0 + bcol);
        }
        __syncthreads();

        #pragma unroll
        for (int k = 0; k < 8; k++) {
            float4 a0 = *reinterpret_cast<const float4*>(&As[k][ty*8]);
            float4 a1 = *reinterpret_cast<const float4*>(&As[k][ty*8+4]);
            float4 b0 = *reinterpret_cast<const float4*>(&Bs[k][tx*8]);
            float4 b1 = *reinterpret_cast<const float4*>(&Bs[k][tx*8+4]);
            float aa[8] = {a0.x,a0.y,a0.z,a0.w,a1.x,a1.y,a1.z,a1.w};
            float bb[8] = {b0.x,b0.y,b0.z,b0.w,b1.x,b1.y,b1.z,b1.w};
            #pragma unroll
            for (int i = 0; i < 8; i++)
                #pragma unroll
                for (int j = 0; j < 8; j++) acc[i][j] += aa[i]*bb[j];
        }
        __syncthreads();
    }

    #pragma unroll
    for (int i = 0; i < 8; i++) {
        int gm = m0 + ty*8 + i;
        if (gm >= M) continue;
        #pragma unroll
        for (int j = 0; j < 8; j++) {
            int gn = n0 + tx*8 + j;
            float v = acc[i][j] + bias[gn];
            if (resid) v += resid[(size_t)gm*N + gn];
            if (act)   v = 0.5f*v*(1.0f + erff(v*0.70710678118654752f));
            C[(size_t)gm*N + gn] = v;
        }
    }
}

// ---------------- attention: one block per (b, h) ----------------
// smem: Kh[197*65], Vh[197*65], srow[8*200], qrow[8*64]
#define ATT_SMEM_FLOATS (197*65*2 + 8*200 + 8*64)
__global__ __launch_bounds__(256) void attention_k(
    const float* __restrict__ q, const float* __restrict__ k,
    const float* __restrict__ v, float* __restrict__ att)
{
    extern __shared__ float sm[];
    float* Kh   = sm;
    float* Vh   = sm + 197*65;
    float* srow = Vh + 197*65;
    float* qrow = srow + 8*200;

    int bh = blockIdx.x;
    int b = bh / NH, h = bh % NH;
    int tid = threadIdx.x, wid = tid >> 5, lane = tid & 31;

    const float* kbase = k + (size_t)(b*SEQ)*HID + h*DH;
    const float* vbase = v + (size_t)(b*SEQ)*HID + h*DH;
    for (int idx = tid; idx < SEQ*DH; idx += 256) {
        int t = idx >> 6, dk = idx & 63;
        Kh[t*65 + dk] = kbase[(size_t)t*HID + dk];
        Vh[t*65 + dk] = vbase[(size_t)t*HID + dk];
    }
    __syncthreads();

    const float* qbase = q + (size_t)(b*SEQ)*HID + h*DH;
    float* obase = att + (size_t)(b*SEQ)*HID + h*DH;
    float* myS = srow + wid*200;
    float* myQ = qrow + wid*64;

    for (int s = wid; s < SEQ; s += 8) {
        myQ[lane]      = qbase[(size_t)s*HID + lane];
        myQ[lane + 32] = qbase[(size_t)s*HID + lane + 32];
        __syncwarp();

        float sc[7];
        float mx = -1e30f;
        #pragma unroll
        for (int i = 0; i < 7; i++) {
            int t = lane + 32*i;
            float d = -1e30f;
            if (t < SEQ) {
                d = 0.0f;
                #pragma unroll
                for (int dk = 0; dk < 64; dk++) d += myQ[dk] * Kh[t*65 + dk];
                d *= 0.125f;
            }
            sc[i] = d;
            mx = fmaxf(mx, d);
        }
        #pragma unroll
        for (int o = 16; o > 0; o >>= 1) mx = fmaxf(mx, __shfl_xor_sync(0xffffffffu, mx, o));

        float sum = 0.0f;
        #pragma unroll
        for (int i = 0; i < 7; i++) {
            int t = lane + 32*i;
            float e = (t < SEQ) ? expf(sc[i] - mx) : 0.0f;
            sc[i] = e; sum += e;
        }
        #pragma unroll
        for (int o = 16; o > 0; o >>= 1) sum += __shfl_xor_sync(0xffffffffu, sum, o);
        float inv = 1.0f / sum;

        #pragma unroll
        for (int i = 0; i < 7; i++) {
            int t = lane + 32*i;
            if (t < SEQ) myS[t] = sc[i]*inv;
        }
        __syncwarp();

        float a0 = 0.0f, a1 = 0.0f;
        for (int t = 0; t < SEQ; t++) {
            float p = myS[t];
            a0 += p * Vh[t*65 + lane];
            a1 += p * Vh[t*65 + lane + 32];
        }
        obase[(size_t)s*HID + lane]      = a0;
        obase[(size_t)s*HID + lane + 32] = a1;
        __syncwarp();
    }
}

// ---------------- classifier head ----------------
__global__ void head_k(const float* __restrict__ h, const float* __restrict__ W,
                       const float* __restrict__ bias, float* __restrict__ out) {
    __shared__ float row[HID];
    int b = blockIdx.y;
    int n = blockIdx.x*256 + threadIdx.x;
    const float* hr = h + (size_t)(b*SEQ)*HID;
    for (int i = threadIdx.x; i < HID; i += 256) row[i] = hr[i];
    __syncthreads();
    if (n < NCLS) {
        float acc = bias[n];
        for (int d = 0; d < HID; d++) acc += row[d] * W[(size_t)d*NCLS + n];
        out[(size_t)b*NCLS + n] = acc;
    }
}

// ---------------- host orchestration ----------------
static float* sym_addr(const void* sym) {
    void* p = nullptr;
    cudaGetSymbolAddress(&p, sym);
    return (float*)p;
}

extern "C" void kernel_launch(void* const* d_in, const int* in_sizes, int n_in,
                              void* d_out, int out_size) {
    const float* x      = (const float*)d_in[0];
    const float* conv_w = (const float*)d_in[1];
    const float* conv_b = (const float*)d_in[2];
    const float* cls    = (const float*)d_in[3];
    const float* pos    = (const float*)d_in[4];
    const float* ln1_s  = (const float*)d_in[5];
    const float* ln1_b  = (const float*)d_in[6];
    const float* wq     = (const float*)d_in[7];
    const float* bq     = (const float*)d_in[8];
    const float* wk     = (const float*)d_in[9];
    const float* bk     = (const float*)d_in[10];
    const float* wv     = (const float*)d_in[11];
    const float* bv     = (const float*)d_in[12];
    const float* wo     = (const float*)d_in[13];
    const float* bo     = (const float*)d_in[14];
    const float* ln2_s  = (const float*)d_in[15];
    const float* ln2_b  = (const float*)d_in[16];
    const float* w1     = (const float*)d_in[17];
    const float* b1     = (const float*)d_in[18];
    const float* w2     = (const float*)d_in[19];
    const float* b2     = (const float*)d_in[20];
    const float* head_w = (const float*)d_in[21];
    const float* head_b = (const float*)d_in[22];
    float* out = (float*)d_out;

    float* h_   = sym_addr(g_h);
    float* hn_  = sym_addr(g_hn);
    float* q_   = sym_addr(g_q);
    float* k_   = sym_addr(g_k);
    float* v_   = sym_addr(g_v);
    float* att_ = sym_addr(g_att);
    float* m1_  = sym_addr(g_m1);
    float* xp_  = sym_addr(g_xp);
    float* wp_  = sym_addr(g_wp);

    const int ATT_SMEM = ATT_SMEM_FLOATS * (int)sizeof(float);
    cudaFuncSetAttribute(attention_k, cudaFuncAttributeMaxDynamicSharedMemorySize, ATT_SMEM);

    // ---- patch embedding ----
    transpose_w<<<(HID*HID + 255)/256, 256>>>(conv_w, wp_);
    patchify<<<(MPATCH*HID + 255)/256, 256>>>(x, xp_);
    {   // xe = xp @ wp + conv_b   (xe stored into g_att scratch)
        dim3 grid(HID/128, (MPATCH + 127)/128);
        sgemm_k<<<grid, 256>>>(xp_, wp_, att_, MPATCH, HID, HID, HID, 0, conv_b, nullptr, 0);
    }
    build_h<<<(MTOK*HID + 255)/256, 256>>>(att_, cls, pos, h_);

    const int WSTRIDE  = NH*HID*DH;   // per-layer qkv weight stride (589824)
    const int HSTRIDE  = HID*DH;      // per-head block stride (49152)

    for (int l = 0; l < NLAYER; l++) {
        // --- attention block ---
        layernorm_k<<<MTOK, 256>>>(h_, ln1_s + l*HID, ln1_b + l*HID, hn_);
        {
            dim3 grid(HID/128, (MTOK + 127)/128);
            sgemm_k<<<grid, 256>>>(hn_, wq + (size_t)l*WSTRIDE, q_, MTOK, HID, HID, 0, HSTRIDE, bq + l*HID, nullptr, 0);
            sgemm_k<<<grid, 256>>>(hn_, wk + (size_t)l*WSTRIDE, k_, MTOK, HID, HID, 0, HSTRIDE, bk + l*HID, nullptr, 0);
            sgemm_k<<<grid, 256>>>(hn_, wv + (size_t)l*WSTRIDE, v_, MTOK, HID, HID, 0, HSTRIDE, bv + l*HID, nullptr, 0);
        }
        attention_k<<<BATCH*NH, 256, ATT_SMEM>>>(q_, k_, v_, att_);
        {
            dim3 grid(HID/128, (MTOK + 127)/128);
            sgemm_k<<<grid, 256>>>(att_, wo + (size_t)l*HID*HID, h_, MTOK, HID, HID, HID, 0, bo + l*HID, h_, 0);
        }
        // --- MLP block ---
        layernorm_k<<<MTOK, 256>>>(h_, ln2_s + l*HID, ln2_b + l*HID, hn_);
        {
            dim3 grid(INTER/128, (MTOK + 127)/128);
            sgemm_k<<<grid, 256>>>(hn_, w1 + (size_t)l*HID*INTER, m1_, MTOK, INTER, HID, INTER, 0, b1 + l*INTER, nullptr, 1);
        }
        {
            dim3 grid(HID/128, (MTOK + 127)/128);
            sgemm_k<<<grid, 256>>>(m1_, w2 + (size_t)l*INTER*HID, h_, MTOK, HID, INTER, HID, 0, b2 + l*HID, h_, 0);
        }
    }

    // ---- classifier head ----
    {
        dim3 grid((NCLS + 255)/256, BATCH);
        head_k<<<grid, 256>>>(h_, head_w, head_b, out);
    }
}